// round 12
// baseline (speedup 1.0000x reference)
#include <cuda.h>
#include <cuda_runtime.h>
#include <cstdint>
#include <cstring>

// ---------------------------------------------------------------------------
// QuantumLayer: out[r] = <psi_r| U† Z5 U |psi_r>, psi_r = x_r / ||x_r||.
// Lightcone of Z5 touches only qubits {3,4,5} (top 3 index bits), so
// M = O (8x8 Hermitian) ⊗ I_8 and
//   out = ( Σ_{a,b} ReO[a][b] * dot(x[8a..], x[8b..]) ) / ||x||^2.
// Persistent kernel. CTA-cooperative 4-stage pipeline fed by tensormap TMA
// (UTMALDG). R11 trap root-caused: dynamic smem base sat at offset 832 (after
// static smem) — not 128B-aligned as UTMALDG requires. Fixed with
// __align__(128) on the extern shared declaration.
// ---------------------------------------------------------------------------

struct c2 { float x, y; };
__device__ __forceinline__ c2 cmul(c2 a, c2 b) { return { a.x*b.x - a.y*b.y, a.x*b.y + a.y*b.x }; }
__device__ __forceinline__ c2 cadd(c2 a, c2 b) { return { a.x + b.x, a.y + b.y }; }

struct U2 { c2 m00, m01, m10, m11; };

// qiskit U(theta, phi, lam)
__device__ __forceinline__ U2 u3(float th, float ph, float la) {
    float s, c;   sincosf(0.5f * th, &s, &c);
    float sph, cph; sincosf(ph, &sph, &cph);
    float sla, cla; sincosf(la, &sla, &cla);
    float spl, cpl; sincosf(ph + la, &spl, &cpl);
    U2 u;
    u.m00 = {  c,        0.f     };
    u.m01 = { -cla * s, -sla * s };
    u.m10 = {  cph * s,  sph * s };
    u.m11 = {  cpl * c,  spl * c };
    return u;
}

template <int BIT>
__device__ __forceinline__ void apply1(c2 (&w)[8], U2 u) {
#pragma unroll
    for (int a = 0; a < 8; a++) {
        if (!(a & BIT)) {
            c2 t0 = w[a], t1 = w[a | BIT];
            w[a]       = cadd(cmul(u.m00, t0), cmul(u.m01, t1));
            w[a | BIT] = cadd(cmul(u.m10, t0), cmul(u.m11, t1));
        }
    }
}

static constexpr int WARPS   = 12;
static constexpr int TPB     = WARPS * 32;
static constexpr int TROWS   = 192;                    // rows per stage (16/warp)
static constexpr int STAGES  = 4;
static constexpr int STAGE_F = TROWS * 64;             // 12288 floats
static constexpr int STAGE_B = STAGE_F * 4;            // 49152 bytes
static constexpr int SMEM_BYTES = STAGES * STAGE_B;    // 196608

__global__ void __launch_bounds__(TPB, 1) quadform_kernel(
    const __grid_constant__ CUtensorMap tmap,
    const float* __restrict__ p,
    float* __restrict__ out, int n, int ntiles) {
    // 128B alignment REQUIRED: UTMALDG traps on misaligned smem destination.
    extern __shared__ __align__(128) float smem[];     // [STAGES][STAGE_F]
    __shared__ float C[64];
    __shared__ float Wr[8][8];
    __shared__ float Wi[8][8];
    __shared__ alignas(8) unsigned long long full_b[STAGES];
    __shared__ alignas(8) unsigned long long empty_b[STAGES];

    int tid  = threadIdx.x;
    int wid  = tid >> 5;
    int lane = tid & 31;

    uint32_t smem_u  = (uint32_t)__cvta_generic_to_shared(smem);
    uint32_t full_u  = (uint32_t)__cvta_generic_to_shared(&full_b[0]);
    uint32_t empty_u = (uint32_t)__cvta_generic_to_shared(&empty_b[0]);

    int G = gridDim.x;

    if (tid == 0) {
#pragma unroll
        for (int s = 0; s < STAGES; s++) {
            asm volatile("mbarrier.init.shared.b64 [%0], 1;"
                         :: "r"(full_u + s * 8) : "memory");
            asm volatile("mbarrier.init.shared.b64 [%0], %1;"
                         :: "r"(empty_u + s * 8), "r"(WARPS) : "memory");
        }
        asm volatile("fence.proxy.async.shared::cta;" ::: "memory");
    }
    __syncthreads();

    // TMA tensormap load: stage s <- 64x192 box at row tt*TROWS.
    // OOB rows are zero-filled by TMA, so complete_tx is always the full box.
    auto issue = [&](int tt, int s) {
        uint32_t mb = full_u + s * 8;
        asm volatile("mbarrier.arrive.expect_tx.shared.b64 _, [%0], %1;"
                     :: "r"(mb), "r"(STAGE_B) : "memory");
        uint32_t dst = smem_u + s * STAGE_B;
        int y = tt * TROWS;
        asm volatile(
            "cp.async.bulk.tensor.2d.shared::cta.global.tile.mbarrier::complete_tx::bytes "
            "[%0], [%1, {%2, %3}], [%4];"
            :: "r"(dst), "l"(&tmap), "r"(0), "r"(y), "r"(mb) : "memory");
    };

    auto wait_bar = [&](uint32_t mb, int phase) {
        asm volatile(
            "{\n\t.reg .pred P;\n\t"
            "WAIT_%=:\n\t"
            "mbarrier.try_wait.parity.acquire.cta.shared::cta.b64 P, [%0], %1, 0x989680;\n\t"
            "@!P bra WAIT_%=;\n\t}"
            :: "r"(mb), "r"(phase) : "memory");
    };

    // ---- prologue: fill stages 0..2 ----
    if (tid == 0) {
#pragma unroll
        for (int s = 0; s < STAGES - 1; s++) {
            int tt = blockIdx.x + s * G;
            if (tt < ntiles) issue(tt, s);
        }
    }

    // ---- build ReO while first stages stream ----
    // 3-qubit index a: bit0=q3, bit1=q4, bit2=q5. Sub-circuit (forward):
    // U3(q3;9), U3(q4;12), U3(q5;15), CX(4->3), P(19;q3), U3(q3;26),
    // U3(q5;29), CU(35;3->5). O = W† diag(z) W, z_a = +1 iff (a&4)==0.
    if (tid < 8) {
        c2 w[8];
#pragma unroll
        for (int a = 0; a < 8; a++) w[a] = { (a == tid) ? 1.f : 0.f, 0.f };

        apply1<1>(w, u3(p[9],  p[10], p[11]));
        apply1<2>(w, u3(p[12], p[13], p[14]));
        apply1<4>(w, u3(p[15], p[16], p[17]));

        // CX control q4 (bit1) -> target q3 (bit0)
#pragma unroll
        for (int a = 0; a < 8; a++)
            if ((a & 2) && !(a & 1)) { c2 tmp = w[a]; w[a] = w[a | 1]; w[a | 1] = tmp; }

        // P(params[19]) on q3 (bit0)
        {
            float sp, cp; sincosf(p[19], &sp, &cp);
            c2 e = { cp, sp };
#pragma unroll
            for (int a = 0; a < 8; a++) if (a & 1) w[a] = cmul(w[a], e);
        }

        apply1<1>(w, u3(p[26], p[27], p[28]));
        apply1<4>(w, u3(p[29], p[30], p[31]));

        // CU(params 35..37): control q3 (bit0) -> target q5 (bit2)
        {
            U2 u = u3(p[35], p[36], p[37]);
#pragma unroll
            for (int a = 0; a < 8; a++) {
                if ((a & 1) && !(a & 4)) {
                    c2 t0c = w[a], t1c = w[a | 4];
                    w[a]     = cadd(cmul(u.m00, t0c), cmul(u.m01, t1c));
                    w[a | 4] = cadd(cmul(u.m10, t0c), cmul(u.m11, t1c));
                }
            }
        }

#pragma unroll
        for (int a = 0; a < 8; a++) { Wr[a][tid] = w[a].x; Wi[a][tid] = w[a].y; }
    }
    __syncthreads();
    if (tid < 64) {
        int a = tid >> 3, b = tid & 7;
        float acc = 0.f;
#pragma unroll
        for (int c = 0; c < 8; c++) {
            float z = (c & 4) ? -1.f : 1.f;
            acc += z * (Wr[c][a] * Wr[c][b] + Wi[c][a] * Wi[c][b]);
        }
        C[tid] = (a == b) ? acc : 2.f * acc;   // off-diagonals counted twice
    }
    __syncthreads();

    int r_loc = lane >> 1;          // row within warp's 16-row slice
    int h     = lane & 1;           // half: k in {4h..4h+3} of each 8-block

    // ---- pipelined main loop ----
    int it = 0;
    for (int tt = blockIdx.x; tt < ntiles; tt += G, it++) {
        int s = it & 3;

        // producer: issue 3 stages ahead (with empty-stage backpressure)
        if (tid == 0) {
            int ft = tt + 3 * G;
            if (ft < ntiles) {
                int sf = (it + 3) & 3;
                int kf = (it + 3) >> 2;
                if (kf > 0) wait_bar(empty_u + sf * 8, (kf - 1) & 1);
                issue(ft, sf);
            }
        }

        // consumer: wait for stage fill
        wait_bar(full_u + s * 8, (it >> 2) & 1);

        int row = tt * TROWS + wid * 16 + r_loc;
        if (row < n) {
            // half-row from LINEAR layout, rotated chunk order: within each
            // 8-lane LDS.128 phase rows r..r+3 x halves hit distinct banks.
            float x[32];
            const float* rp = smem + s * STAGE_F + (wid * 16 + r_loc) * 64 + 4 * h;
#pragma unroll
            for (int i = 0; i < 8; i++) {
                int c = (i + r_loc) & 7;
                float4 v = *reinterpret_cast<const float4*>(rp + 8 * c);
                x[4*c + 0] = v.x; x[4*c + 1] = v.y; x[4*c + 2] = v.z; x[4*c + 3] = v.w;
            }

            float Q = 0.f, N = 0.f;
#pragma unroll
            for (int a = 0; a < 8; a++) {
#pragma unroll
                for (int b = a; b < 8; b++) {
                    float s2 = 0.f;
#pragma unroll
                    for (int k = 0; k < 4; k++) s2 += x[4*a + k] * x[4*b + k];
                    Q += C[8*a + b] * s2;
                    if (a == b) N += s2;
                }
            }
            // combine the two half-rows
            Q += __shfl_xor_sync(0xFFFFFFFF, Q, 1);
            N += __shfl_xor_sync(0xFFFFFFFF, N, 1);
            if (h == 0) {
                // jnp.isclose(norm,0), atol=1e-8 -> N <= 1e-16 -> psi = e0
                out[row] = (N <= 1e-16f) ? C[0] : (Q / N);
            }
        }
        __syncwarp();   // all lanes done reading stage s
        if (lane == 0) {
            asm volatile("mbarrier.arrive.shared.b64 _, [%0];"
                         :: "r"(empty_u + s * 8) : "memory");
        }
    }
}

// ---------------------------------------------------------------------------

typedef CUresult (*EncodeFn)(
    CUtensorMap*, CUtensorMapDataType, cuuint32_t, void*,
    const cuuint64_t*, const cuuint64_t*, const cuuint32_t*, const cuuint32_t*,
    CUtensorMapInterleave, CUtensorMapSwizzle, CUtensorMapL2promotion,
    CUtensorMapFloatOOBfill);

extern "C" void kernel_launch(void* const* d_in, const int* in_sizes, int n_in,
                              void* d_out, int out_size) {
    // metadata order: features (B*64 floats), params (54 floats); be defensive.
    int fi = 0, pi = 1;
    if (n_in >= 2 && in_sizes[0] == 54) { fi = 1; pi = 0; }

    float* feat = (float*)d_in[fi];
    const float* params = (const float*)d_in[pi];
    float* out = (float*)d_out;

    int n = in_sizes[fi] / 64;
    int ntiles = (n + TROWS - 1) / TROWS;

    // Resolve cuTensorMapEncodeTiled through cudart (no -lcuda needed).
    static EncodeFn encode = nullptr;
    if (!encode) {
        void* fp = nullptr;
        cudaDriverEntryPointQueryResult st;
        cudaGetDriverEntryPoint("cuTensorMapEncodeTiled", &fp,
                                cudaEnableDefault, &st);
        encode = (EncodeFn)fp;
    }

    // 2D tensor: [64 floats contiguous] x [n rows], row stride 256 B.
    CUtensorMap tmap;
    memset(&tmap, 0, sizeof(tmap));
    cuuint64_t dims[2]    = { 64, (cuuint64_t)n };
    cuuint64_t strides[1] = { 256 };
    cuuint32_t box[2]     = { 64, TROWS };
    cuuint32_t estr[2]    = { 1, 1 };
    encode(&tmap, CU_TENSOR_MAP_DATA_TYPE_FLOAT32, 2, feat,
           dims, strides, box, estr,
           CU_TENSOR_MAP_INTERLEAVE_NONE, CU_TENSOR_MAP_SWIZZLE_NONE,
           CU_TENSOR_MAP_L2_PROMOTION_L2_256B,
           CU_TENSOR_MAP_FLOAT_OOB_FILL_NONE);

    cudaFuncSetAttribute(quadform_kernel,
                         cudaFuncAttributeMaxDynamicSharedMemorySize, SMEM_BYTES);

    // 1 block/SM (192 KB dynamic smem), persistent
    int grid = 148;
    if (grid > ntiles) grid = ntiles;

    quadform_kernel<<<grid, TPB, SMEM_BYTES>>>(tmap, params, out, n, ntiles);
}

// round 13
// speedup vs baseline: 2.0706x; 2.0706x over previous
#include <cuda.h>
#include <cuda_runtime.h>
#include <cstdint>
#include <cstring>

// ---------------------------------------------------------------------------
// QuantumLayer: out[r] = <psi_r| U† Z5 U |psi_r>, psi_r = x_r / ||x_r||.
// Lightcone of Z5 touches only qubits {3,4,5} (top 3 index bits), so
// M = O (8x8 Hermitian) ⊗ I_8 and
//   out = ( Σ_{a,b} ReO[a][b] * dot(x[8a..], x[8b..]) ) / ||x||^2.
//
// HYBRID LOAD-PATH kernel. Measured caps on this chip:
//   SM-issued loads (LDG/LDGSTS, any flavor): ~3.8-4.0 TB/s (L1tex fill cap)
//   TMA (UBLKCP / UTMALDG, any request size): ~1.2 TB/s (engine cap)
// These sit in different HW domains -> drive BOTH concurrently.
//   warps 0-11 : per-warp LDGSTS double-buffer pipelines, rows [0, ldg_rows)
//   warps 12-15: TMA 4-stage mbarrier ring (warp12/lane0 produces),
//                rows [ldg_rows, n) in 64-row boxes
// ---------------------------------------------------------------------------

struct c2 { float x, y; };
__device__ __forceinline__ c2 cmul(c2 a, c2 b) { return { a.x*b.x - a.y*b.y, a.x*b.y + a.y*b.x }; }
__device__ __forceinline__ c2 cadd(c2 a, c2 b) { return { a.x + b.x, a.y + b.y }; }

struct U2 { c2 m00, m01, m10, m11; };

// qiskit U(theta, phi, lam)
__device__ __forceinline__ U2 u3(float th, float ph, float la) {
    float s, c;   sincosf(0.5f * th, &s, &c);
    float sph, cph; sincosf(ph, &sph, &cph);
    float sla, cla; sincosf(la, &sla, &cla);
    float spl, cpl; sincosf(ph + la, &spl, &cpl);
    U2 u;
    u.m00 = {  c,        0.f     };
    u.m01 = { -cla * s, -sla * s };
    u.m10 = {  cph * s,  sph * s };
    u.m11 = {  cpl * c,  spl * c };
    return u;
}

template <int BIT>
__device__ __forceinline__ void apply1(c2 (&w)[8], U2 u) {
#pragma unroll
    for (int a = 0; a < 8; a++) {
        if (!(a & BIT)) {
            c2 t0 = w[a], t1 = w[a | BIT];
            w[a]       = cadd(cmul(u.m00, t0), cmul(u.m01, t1));
            w[a | BIT] = cadd(cmul(u.m10, t0), cmul(u.m11, t1));
        }
    }
}

static constexpr int WARPS_L = 12;              // LDGSTS warps
static constexpr int TPB     = 512;             // 16 warps total
// LDG side: 16-row warp tiles, padded rows
static constexpr int WROWS   = 16;
static constexpr int ROW_PAD = 72;              // STS.128 + strided LDS.128 conflict-free
static constexpr int WTILE   = WROWS * ROW_PAD;                 // 1152 floats
static constexpr int LDG_SMEM_F = WARPS_L * 2 * WTILE;          // 27648 floats = 110592 B
// TMA side: 64-row stages, linear layout
static constexpr int TROWS_T = 64;
static constexpr int STAGES  = 4;
static constexpr int STAGE_F = TROWS_T * 64;                    // 4096 floats
static constexpr int STAGE_B = STAGE_F * 4;                     // 16384 B
static constexpr int TMA_OFF_F = LDG_SMEM_F;                    // 128B-aligned (110592 % 128 == 0)
static constexpr int SMEM_BYTES = (LDG_SMEM_F + STAGES * STAGE_F) * 4;  // 176128

__global__ void __launch_bounds__(TPB, 1) quadform_kernel(
    const __grid_constant__ CUtensorMap tmap,
    const float* __restrict__ feat, const float* __restrict__ p,
    float* __restrict__ out, int n,
    int ldg_rows, int nltiles, int ntma) {
    extern __shared__ __align__(128) float smem[];
    __shared__ float C[64];
    __shared__ float Wr[8][8];
    __shared__ float Wi[8][8];
    __shared__ alignas(8) unsigned long long full_b[STAGES];
    __shared__ alignas(8) unsigned long long empty_b[STAGES];

    int tid  = threadIdx.x;
    int wid  = tid >> 5;
    int lane = tid & 31;
    int G = gridDim.x;

    uint32_t full_u  = (uint32_t)__cvta_generic_to_shared(&full_b[0]);
    uint32_t empty_u = (uint32_t)__cvta_generic_to_shared(&empty_b[0]);
    uint32_t tma_u   = (uint32_t)__cvta_generic_to_shared(smem + TMA_OFF_F);

    // ---- mbarrier init ----
    if (tid == 0) {
#pragma unroll
        for (int s = 0; s < STAGES; s++) {
            asm volatile("mbarrier.init.shared.b64 [%0], 1;"
                         :: "r"(full_u + s * 8) : "memory");
            asm volatile("mbarrier.init.shared.b64 [%0], %1;"
                         :: "r"(empty_u + s * 8), "r"(4) : "memory");
        }
        asm volatile("fence.proxy.async.shared::cta;" ::: "memory");
    }
    __syncthreads();

    auto wait_bar = [&](uint32_t mb, int phase) {
        asm volatile(
            "{\n\t.reg .pred P;\n\t"
            "WAIT_%=:\n\t"
            "mbarrier.try_wait.parity.acquire.cta.shared::cta.b64 P, [%0], %1, 0x989680;\n\t"
            "@!P bra WAIT_%=;\n\t}"
            :: "r"(mb), "r"(phase) : "memory");
    };

    // TMA: issue 64-row box (rows ldg_rows + tt*64 ...) into stage s
    auto tma_issue = [&](int tt, int s) {
        uint32_t mb = full_u + s * 8;
        asm volatile("mbarrier.arrive.expect_tx.shared.b64 _, [%0], %1;"
                     :: "r"(mb), "r"(STAGE_B) : "memory");
        uint32_t dst = tma_u + s * STAGE_B;
        int y = ldg_rows + tt * TROWS_T;
        asm volatile(
            "cp.async.bulk.tensor.2d.shared::cta.global.tile.mbarrier::complete_tx::bytes "
            "[%0], [%1, {%2, %3}], [%4];"
            :: "r"(dst), "l"(&tmap), "r"(0), "r"(y), "r"(mb) : "memory");
    };

    // ---- TMA prologue: fill stages 0..2 (producer = tid 384) ----
    if (tid == WARPS_L * 32) {
#pragma unroll
        for (int s = 0; s < STAGES - 1; s++) {
            int tt = blockIdx.x + s * G;
            if (tt < ntma) tma_issue(tt, s);
        }
    }

    // ---- LDG side: kick off first prefetches ----
    float* wtile = smem + wid * (2 * WTILE);        // valid for wid < 12
    uint64_t pol;
    asm("createpolicy.fractional.L2::evict_last.b64 %0, 1.0;" : "=l"(pol));

    auto ldg_prefetch = [&](int tt, int buf) {
        int base = tt * WROWS;
        const float4* src = reinterpret_cast<const float4*>(feat) + (size_t)base * 16;
        float* dstf = wtile + buf * WTILE;
        int rows = ldg_rows - base;
        int nvec = (rows >= WROWS ? WROWS : (rows > 0 ? rows : 0)) * 16;
#pragma unroll
        for (int i = 0; i < 8; i++) {
            int v = lane + 32 * i;
            if (v < nvec) {
                int r = v >> 4, c4 = v & 15;
                uint32_t d = (uint32_t)__cvta_generic_to_shared(&dstf[r * ROW_PAD + c4 * 4]);
                asm volatile(
                    "cp.async.cg.shared.global.L2::cache_hint [%0], [%1], 16, %2;"
                    :: "r"(d), "l"(src + v), "l"(pol) : "memory");
            }
        }
    };

    int gwarp  = blockIdx.x * WARPS_L + wid;        // LDG warps only
    int nwl    = G * WARPS_L;
    if (wid < WARPS_L) {
        if (gwarp < nltiles) ldg_prefetch(gwarp, 0);
        asm volatile("cp.async.commit_group;" ::: "memory");
    }

    // ---- build ReO while data streams ----
    // 3-qubit index a: bit0=q3, bit1=q4, bit2=q5. Sub-circuit (forward):
    // U3(q3;9), U3(q4;12), U3(q5;15), CX(4->3), P(19;q3), U3(q3;26),
    // U3(q5;29), CU(35;3->5). O = W† diag(z) W, z_a = +1 iff (a&4)==0.
    if (tid < 8) {
        c2 w[8];
#pragma unroll
        for (int a = 0; a < 8; a++) w[a] = { (a == tid) ? 1.f : 0.f, 0.f };

        apply1<1>(w, u3(p[9],  p[10], p[11]));
        apply1<2>(w, u3(p[12], p[13], p[14]));
        apply1<4>(w, u3(p[15], p[16], p[17]));
#pragma unroll
        for (int a = 0; a < 8; a++)
            if ((a & 2) && !(a & 1)) { c2 tmp = w[a]; w[a] = w[a | 1]; w[a | 1] = tmp; }
        {
            float sp, cp; sincosf(p[19], &sp, &cp);
            c2 e = { cp, sp };
#pragma unroll
            for (int a = 0; a < 8; a++) if (a & 1) w[a] = cmul(w[a], e);
        }
        apply1<1>(w, u3(p[26], p[27], p[28]));
        apply1<4>(w, u3(p[29], p[30], p[31]));
        {
            U2 u = u3(p[35], p[36], p[37]);
#pragma unroll
            for (int a = 0; a < 8; a++) {
                if ((a & 1) && !(a & 4)) {
                    c2 t0c = w[a], t1c = w[a | 4];
                    w[a]     = cadd(cmul(u.m00, t0c), cmul(u.m01, t1c));
                    w[a | 4] = cadd(cmul(u.m10, t0c), cmul(u.m11, t1c));
                }
            }
        }
#pragma unroll
        for (int a = 0; a < 8; a++) { Wr[a][tid] = w[a].x; Wi[a][tid] = w[a].y; }
    }
    __syncthreads();
    if (tid < 64) {
        int a = tid >> 3, b = tid & 7;
        float acc = 0.f;
#pragma unroll
        for (int c = 0; c < 8; c++) {
            float z = (c & 4) ? -1.f : 1.f;
            acc += z * (Wr[c][a] * Wr[c][b] + Wi[c][a] * Wi[c][b]);
        }
        C[tid] = (a == b) ? acc : 2.f * acc;
    }
    __syncthreads();   // last block-wide barrier

    int r_loc = lane >> 1;          // row within 16-row slice
    int h     = lane & 1;           // half: k in {4h..4h+3} of each 8-block

    // shared compute: half-row quadratic form from smem row rp (rotate=rot)
    auto compute_row = [&](const float* rp, int rot, int row) {
        float x[32];
#pragma unroll
        for (int i = 0; i < 8; i++) {
            int c = (i + rot) & 7;
            float4 v = *reinterpret_cast<const float4*>(rp + 8 * c);
            x[4*c + 0] = v.x; x[4*c + 1] = v.y; x[4*c + 2] = v.z; x[4*c + 3] = v.w;
        }
        float Q = 0.f, N = 0.f;
#pragma unroll
        for (int a = 0; a < 8; a++) {
#pragma unroll
            for (int b = a; b < 8; b++) {
                float s2 = 0.f;
#pragma unroll
                for (int k = 0; k < 4; k++) s2 += x[4*a + k] * x[4*b + k];
                Q += C[8*a + b] * s2;
                if (a == b) N += s2;
            }
        }
        Q += __shfl_xor_sync(0xFFFFFFFF, Q, 1);
        N += __shfl_xor_sync(0xFFFFFFFF, N, 1);
        if (h == 0) out[row] = (N <= 1e-16f) ? C[0] : (Q / N);
    };

    if (wid < WARPS_L) {
        // ================= LDG role =================
        int buf = 0;
        for (int tt = gwarp; tt < nltiles; tt += nwl) {
            int nxt = tt + nwl;
            if (nxt < nltiles) ldg_prefetch(nxt, buf ^ 1);
            asm volatile("cp.async.commit_group;" ::: "memory");
            asm volatile("cp.async.wait_group 1;" ::: "memory");
            __syncwarp();

            int row = tt * WROWS + r_loc;
            if (row < ldg_rows)
                compute_row(wtile + buf * WTILE + r_loc * ROW_PAD + 4 * h, 0, row);
            __syncwarp();
            buf ^= 1;
        }
        // drain
        asm volatile("cp.async.wait_group 0;" ::: "memory");
    } else {
        // ================= TMA role =================
        int wq = wid - WARPS_L;     // 0..3: quarter of each 64-row stage
        int it = 0;
        for (int tt = blockIdx.x; tt < ntma; tt += G, it++) {
            int s = it & 3;
            if (tid == WARPS_L * 32) {       // producer: 3 ahead
                int ft = tt + 3 * G;
                if (ft < ntma) {
                    int j = it + 3;
                    int sf = j & 3, kf = j >> 2;
                    if (kf > 0) wait_bar(empty_u + sf * 8, (kf - 1) & 1);
                    tma_issue(ft, sf);
                }
            }
            wait_bar(full_u + s * 8, (it >> 2) & 1);

            int lrow = wq * 16 + r_loc;                    // row within stage
            int row  = ldg_rows + tt * TROWS_T + lrow;     // global (always < n)
            compute_row(smem + TMA_OFF_F + s * STAGE_F + lrow * 64 + 4 * h,
                        r_loc, row);
            __syncwarp();
            if (lane == 0) {
                asm volatile("mbarrier.arrive.shared.b64 _, [%0];"
                             :: "r"(empty_u + s * 8) : "memory");
            }
        }
    }
}

// ---------------------------------------------------------------------------

typedef CUresult (*EncodeFn)(
    CUtensorMap*, CUtensorMapDataType, cuuint32_t, void*,
    const cuuint64_t*, const cuuint64_t*, const cuuint32_t*, const cuuint32_t*,
    CUtensorMapInterleave, CUtensorMapSwizzle, CUtensorMapL2promotion,
    CUtensorMapFloatOOBfill);

extern "C" void kernel_launch(void* const* d_in, const int* in_sizes, int n_in,
                              void* d_out, int out_size) {
    int fi = 0, pi = 1;
    if (n_in >= 2 && in_sizes[0] == 54) { fi = 1; pi = 0; }

    float* feat = (float*)d_in[fi];
    const float* params = (const float*)d_in[pi];
    float* out = (float*)d_out;

    int n = in_sizes[fi] / 64;

    // rate split: TMA ~1.2 TB/s vs LDG ~3.8 TB/s -> TMA takes ~24%
    int ntma = (int)(((long long)n * 24) / 100) / TROWS_T;   // 64-row tiles
    if (ntma < 0) ntma = 0;
    int ldg_rows = n - ntma * TROWS_T;
    int nltiles  = (ldg_rows + WROWS - 1) / WROWS;

    static EncodeFn encode = nullptr;
    if (!encode) {
        void* fp = nullptr;
        cudaDriverEntryPointQueryResult st;
        cudaGetDriverEntryPoint("cuTensorMapEncodeTiled", &fp,
                                cudaEnableDefault, &st);
        encode = (EncodeFn)fp;
    }

    CUtensorMap tmap;
    memset(&tmap, 0, sizeof(tmap));
    cuuint64_t dims[2]    = { 64, (cuuint64_t)n };
    cuuint64_t strides[1] = { 256 };
    cuuint32_t box[2]     = { 64, TROWS_T };
    cuuint32_t estr[2]    = { 1, 1 };
    encode(&tmap, CU_TENSOR_MAP_DATA_TYPE_FLOAT32, 2, feat,
           dims, strides, box, estr,
           CU_TENSOR_MAP_INTERLEAVE_NONE, CU_TENSOR_MAP_SWIZZLE_NONE,
           CU_TENSOR_MAP_L2_PROMOTION_L2_256B,
           CU_TENSOR_MAP_FLOAT_OOB_FILL_NONE);

    cudaFuncSetAttribute(quadform_kernel,
                         cudaFuncAttributeMaxDynamicSharedMemorySize, SMEM_BYTES);

    int grid = 148;   // 1 persistent block/SM
    quadform_kernel<<<grid, TPB, SMEM_BYTES>>>(
        tmap, feat, params, out, n, ldg_rows, nltiles, ntma);
}

// round 14
// speedup vs baseline: 3.1157x; 1.5047x over previous
#include <cuda_runtime.h>
#include <cuda_pipeline.h>
#include <cstdint>

// ---------------------------------------------------------------------------
// QuantumLayer: out[r] = <psi_r| U† Z5 U |psi_r>, psi_r = x_r / ||x_r||.
// Lightcone of Z5 touches only qubits {3,4,5} (top 3 index bits), so
// M = O (8x8 Hermitian) ⊗ I_8 and
//   out = ( Σ_{a,b} ReO[a][b] * dot(x[8a..], x[8b..]) ) / ||x||^2.
//
// Final form. Persistent kernel, per-warp cp.async double-buffered pipelines,
// half-row-per-lane compute (24 warps/SM). Measured across 11 structural
// variants: every fill path (LDG.ca/LDGSTS/LDG.cv/TMA) saturates the per-SM
// fill port at ~27 GB/s/SM -> ~4.0 TB/s chip; this kernel runs at that floor.
// ---------------------------------------------------------------------------

struct c2 { float x, y; };
__device__ __forceinline__ c2 cmul(c2 a, c2 b) { return { a.x*b.x - a.y*b.y, a.x*b.y + a.y*b.x }; }
__device__ __forceinline__ c2 cadd(c2 a, c2 b) { return { a.x + b.x, a.y + b.y }; }

struct U2 { c2 m00, m01, m10, m11; };

// qiskit U(theta, phi, lam)
__device__ __forceinline__ U2 u3(float th, float ph, float la) {
    float s, c;   sincosf(0.5f * th, &s, &c);
    float sph, cph; sincosf(ph, &sph, &cph);
    float sla, cla; sincosf(la, &sla, &cla);
    float spl, cpl; sincosf(ph + la, &spl, &cpl);
    U2 u;
    u.m00 = {  c,        0.f     };
    u.m01 = { -cla * s, -sla * s };
    u.m10 = {  cph * s,  sph * s };
    u.m11 = {  cpl * c,  spl * c };
    return u;
}

template <int BIT>
__device__ __forceinline__ void apply1(c2 (&w)[8], U2 u) {
#pragma unroll
    for (int a = 0; a < 8; a++) {
        if (!(a & BIT)) {
            c2 t0 = w[a], t1 = w[a | BIT];
            w[a]       = cadd(cmul(u.m00, t0), cmul(u.m01, t1));
            w[a | BIT] = cadd(cmul(u.m10, t0), cmul(u.m11, t1));
        }
    }
}

static constexpr int WARPS   = 8;     // per block
static constexpr int TPB     = WARPS * 32;
static constexpr int WROWS   = 16;    // rows per warp-tile (2 lanes per row)
static constexpr int ROW_PAD = 72;    // 64+8 floats: conflict-free for both
                                      // STS.128 and strided LDS.128
static constexpr int WTILE   = WROWS * ROW_PAD;              // floats/stage
static constexpr int SMEM_BYTES = WARPS * 2 * WTILE * 4;     // 73728

__global__ void __launch_bounds__(TPB, 3) quadform_kernel(
    const float* __restrict__ feat, const float* __restrict__ p,
    float* __restrict__ out, int n, int ntiles, int full_tiles) {
    extern __shared__ float smem[];            // [WARPS][2][WTILE]
    __shared__ float C[64];
    __shared__ float Wr[8][8];
    __shared__ float Wi[8][8];

    int tid  = threadIdx.x;
    int wid  = tid >> 5;
    int lane = tid & 31;
    float* wtile = smem + wid * (2 * WTILE);

    int gwarp  = blockIdx.x * WARPS + wid;
    int nwarps = gridDim.x * WARPS;

    // L2 evict_last policy (kept: measured best-equal variant, R8)
    uint64_t pol;
    asm("createpolicy.fractional.L2::evict_last.b64 %0, 1.0;" : "=l"(pol));

    // warp-private prefetch of 16-row tile tt into stage buf (cp.async.cg)
    auto prefetch = [&](int tt, int buf) {
        int base = tt * WROWS;
        const float4* src = reinterpret_cast<const float4*>(feat) + (size_t)base * 16;
        float* dstf = wtile + buf * WTILE;
        if (tt < full_tiles) {               // common case: no bounds checks
#pragma unroll
            for (int i = 0; i < 8; i++) {
                int v = lane + 32 * i;
                int r = v >> 4, c4 = v & 15;
                uint32_t d = (uint32_t)__cvta_generic_to_shared(&dstf[r * ROW_PAD + c4 * 4]);
                asm volatile(
                    "cp.async.cg.shared.global.L2::cache_hint [%0], [%1], 16, %2;"
                    :: "r"(d), "l"(src + v), "l"(pol) : "memory");
            }
        } else {
            int nvec = (n - base) * 16;
            for (int v = lane; v < nvec; v += 32) {
                int r = v >> 4, c4 = v & 15;
                uint32_t d = (uint32_t)__cvta_generic_to_shared(&dstf[r * ROW_PAD + c4 * 4]);
                asm volatile(
                    "cp.async.cg.shared.global.L2::cache_hint [%0], [%1], 16, %2;"
                    :: "r"(d), "l"(src + v), "l"(pol) : "memory");
            }
        }
    };

    // ---- kick off first prefetch immediately ----
    if (gwarp < ntiles) prefetch(gwarp, 0);
    __pipeline_commit();

    // ---- build ReO while first tiles stream (once per block) ----
    // 3-qubit index a: bit0=q3, bit1=q4, bit2=q5. Sub-circuit (forward):
    // U3(q3;9), U3(q4;12), U3(q5;15), CX(4->3), P(19;q3), U3(q3;26),
    // U3(q5;29), CU(35;3->5). O = W† diag(z) W, z_a = +1 iff (a&4)==0.
    if (tid < 8) {
        c2 w[8];
#pragma unroll
        for (int a = 0; a < 8; a++) w[a] = { (a == tid) ? 1.f : 0.f, 0.f };

        apply1<1>(w, u3(p[9],  p[10], p[11]));
        apply1<2>(w, u3(p[12], p[13], p[14]));
        apply1<4>(w, u3(p[15], p[16], p[17]));

        // CX control q4 (bit1) -> target q3 (bit0)
#pragma unroll
        for (int a = 0; a < 8; a++)
            if ((a & 2) && !(a & 1)) { c2 tmp = w[a]; w[a] = w[a | 1]; w[a | 1] = tmp; }

        // P(params[19]) on q3 (bit0)
        {
            float sp, cp; sincosf(p[19], &sp, &cp);
            c2 e = { cp, sp };
#pragma unroll
            for (int a = 0; a < 8; a++) if (a & 1) w[a] = cmul(w[a], e);
        }

        apply1<1>(w, u3(p[26], p[27], p[28]));
        apply1<4>(w, u3(p[29], p[30], p[31]));

        // CU(params 35..37): control q3 (bit0) -> target q5 (bit2)
        {
            U2 u = u3(p[35], p[36], p[37]);
#pragma unroll
            for (int a = 0; a < 8; a++) {
                if ((a & 1) && !(a & 4)) {
                    c2 t0c = w[a], t1c = w[a | 4];
                    w[a]     = cadd(cmul(u.m00, t0c), cmul(u.m01, t1c));
                    w[a | 4] = cadd(cmul(u.m10, t0c), cmul(u.m11, t1c));
                }
            }
        }

#pragma unroll
        for (int a = 0; a < 8; a++) { Wr[a][tid] = w[a].x; Wi[a][tid] = w[a].y; }
    }
    __syncthreads();
    if (tid < 64) {
        int a = tid >> 3, b = tid & 7;
        float acc = 0.f;
#pragma unroll
        for (int c = 0; c < 8; c++) {
            float z = (c & 4) ? -1.f : 1.f;
            acc += z * (Wr[c][a] * Wr[c][b] + Wi[c][a] * Wi[c][b]);
        }
        C[tid] = (a == b) ? acc : 2.f * acc;   // off-diagonals counted twice
    }
    __syncthreads();   // C visible to all warps; last block-wide barrier

    int r_loc = lane >> 1;          // row within tile
    int h     = lane & 1;           // half: k in {4h..4h+3} of each block

    // ---- per-warp independent pipelined loop ----
    int buf = 0;
    for (int tt = gwarp; tt < ntiles; tt += nwarps) {
        int nxt = tt + nwarps;
        if (nxt < ntiles) prefetch(nxt, buf ^ 1);
        __pipeline_commit();          // uniform group counting
        __pipeline_wait_prior(1);     // current tile complete (this thread)
        __syncwarp();                 // cross-lane visibility within warp

        int row = tt * WROWS + r_loc;
        if (row < n) {
            // half-row: float4 a-th chunk = x[8a + 4h .. 8a + 4h + 3]
            float x[32];
            const float* rp = wtile + buf * WTILE + r_loc * ROW_PAD + 4 * h;
#pragma unroll
            for (int a = 0; a < 8; a++) {
                float4 v = *reinterpret_cast<const float4*>(rp + 8 * a);
                x[4*a + 0] = v.x; x[4*a + 1] = v.y; x[4*a + 2] = v.z; x[4*a + 3] = v.w;
            }

            float Q = 0.f, N = 0.f;
#pragma unroll
            for (int a = 0; a < 8; a++) {
#pragma unroll
                for (int b = a; b < 8; b++) {
                    float s = 0.f;
#pragma unroll
                    for (int k = 0; k < 4; k++) s += x[4*a + k] * x[4*b + k];
                    Q += C[8*a + b] * s;
                    if (a == b) N += s;
                }
            }
            // combine the two half-rows
            Q += __shfl_xor_sync(0xFFFFFFFF, Q, 1);
            N += __shfl_xor_sync(0xFFFFFFFF, N, 1);
            if (h == 0) {
                // jnp.isclose(norm,0), atol=1e-8 -> N <= 1e-16 -> psi = e0
                out[row] = (N <= 1e-16f) ? C[0] : __fdividef(Q, N);
            }
        }
        __syncwarp();                 // all lanes done reading buf before refill
        buf ^= 1;
    }
}

extern "C" void kernel_launch(void* const* d_in, const int* in_sizes, int n_in,
                              void* d_out, int out_size) {
    // metadata order: features (B*64 floats), params (54 floats); be defensive.
    int fi = 0, pi = 1;
    if (n_in >= 2 && in_sizes[0] == 54) { fi = 1; pi = 0; }

    const float* feat   = (const float*)d_in[fi];
    const float* params = (const float*)d_in[pi];
    float* out = (float*)d_out;

    int n = in_sizes[fi] / 64;
    int ntiles = (n + WROWS - 1) / WROWS;
    int full_tiles = n / WROWS;           // tiles with no tail handling

    cudaFuncSetAttribute(quadform_kernel,
                         cudaFuncAttributeMaxDynamicSharedMemorySize, SMEM_BYTES);

    // 3 blocks/SM (73.7 KB dynamic smem each) x 148 SMs = 24 warps/SM
    int grid = 148 * 3;
    int maxgrid = (ntiles + WARPS - 1) / WARPS;
    if (grid > maxgrid) grid = maxgrid;

    quadform_kernel<<<grid, TPB, SMEM_BYTES>>>(feat, params, out, n, ntiles,
                                               full_tiles);
}